// round 8
// baseline (speedup 1.0000x reference)
#include <cuda_runtime.h>
#include <cstdint>

#define N_NODES 65536
#define N_EDGES 524288
#define DIM     512

// Scratch: Y = Adj @ X  (fp32, 128 MB) — static device global (no allocs allowed)
__device__ float g_Y[(size_t)N_NODES * DIM];
// OR of odd 32-bit words of the row-index buffer: ==0  <=>  indices are int64
__device__ unsigned int g_or_hi;

// ---------------------------------------------------------------------------
// Kernel 0: zero Y scratch + reset dtype-detect accumulator
// ---------------------------------------------------------------------------
__global__ void __launch_bounds__(256) zero_kernel() {
    const size_t n4 = (size_t)N_NODES * DIM / 4;
    float4* p = reinterpret_cast<float4*>(g_Y);
    float4 z = make_float4(0.f, 0.f, 0.f, 0.f);
    for (size_t i = (size_t)blockIdx.x * blockDim.x + threadIdx.x; i < n4;
         i += (size_t)gridDim.x * blockDim.x)
        p[i] = z;
    if (blockIdx.x == 0 && threadIdx.x == 0) g_or_hi = 0u;
}

// ---------------------------------------------------------------------------
// Kernel 1: detect int32 vs int64 indices.
// Reads only the first N_EDGES 32-bit words (always in-bounds for both dtypes).
// int64 case: odd words are high halves of entries 0..N_EDGES/2-1 -> all 0.
// int32 case: odd words are random indices in [0,65536) -> OR != 0 w.p. ~1.
// ---------------------------------------------------------------------------
__global__ void __launch_bounds__(256) detect_kernel(const unsigned int* __restrict__ rowu) {
    unsigned int v = 0;
    for (int i = blockIdx.x * blockDim.x + threadIdx.x; i < N_EDGES / 2;
         i += gridDim.x * blockDim.x)
        v |= rowu[2 * i + 1];
    // warp reduce
    #pragma unroll
    for (int s = 16; s > 0; s >>= 1) v |= __shfl_xor_sync(0xFFFFFFFFu, v, s);
    if ((threadIdx.x & 31) == 0 && v) atomicOr(&g_or_hi, v);
}

// ---------------------------------------------------------------------------
// Kernel 2: scatter  Y[row[e]] += vals[e] * x[col[e]]
// One warp per edge; lane l handles float4 chunks l, l+32, l+64, l+96.
// Atomic addresses within a warp are consecutive -> coalesced 128B RMW groups.
// ---------------------------------------------------------------------------
__global__ void __launch_bounds__(256) scatter_kernel(const float* __restrict__ x,
                                                      const void*  __restrict__ rowp,
                                                      const void*  __restrict__ colp,
                                                      const float* __restrict__ vals) {
    const bool is64 = (g_or_hi == 0u);
    int e    = blockIdx.x * (blockDim.x >> 5) + (threadIdx.x >> 5);
    int lane = threadIdx.x & 31;
    if (e >= N_EDGES) return;

    int r, c;
    if (is64) {
        r = (int)reinterpret_cast<const long long*>(rowp)[e];
        c = (int)reinterpret_cast<const long long*>(colp)[e];
    } else {
        r = reinterpret_cast<const int*>(rowp)[e];
        c = reinterpret_cast<const int*>(colp)[e];
    }
    const float v = vals[e];

    const float4* xs = reinterpret_cast<const float4*>(x + (size_t)c * DIM);
    float* yd = g_Y + (size_t)r * DIM;

    #pragma unroll
    for (int i = 0; i < 4; i++) {
        int c4 = lane + 32 * i;          // float4 index within the row
        float4 t = xs[c4];
        int base = c4 * 4;
        atomicAdd(&yd[base + 0], v * t.x);
        atomicAdd(&yd[base + 1], v * t.y);
        atomicAdd(&yd[base + 2], v * t.z);
        atomicAdd(&yd[base + 3], v * t.w);
    }
}

// ---------------------------------------------------------------------------
// Kernel 3: out = Y @ W^T   (M=65536, N=512, K=512, all fp32, K-contiguous)
// Classic 128x128 block tile, K-step 8, double-buffered SMEM, 8x8 per thread.
// blockIdx.x = N-tile (4 values, fastest) so consecutive blocks reuse the same
// Y rows through L2 -> Y streamed from HBM ~once.
// ---------------------------------------------------------------------------
__global__ void __launch_bounds__(256) gemm_kernel(const float* __restrict__ W,
                                                   float* __restrict__ out) {
    __shared__ float As[2][8][128];
    __shared__ float Bs[2][8][128];

    const int bn = blockIdx.x;   // 0..3
    const int bm = blockIdx.y;   // 0..511
    const int tid = threadIdx.x;

    // loader mapping: 128 rows x 8 k = 1024 floats = 256 threads x float4
    const int lrow = tid >> 1;
    const int lk   = (tid & 1) * 4;
    const float* ag = g_Y + ((size_t)(bm * 128 + lrow)) * DIM + lk;
    const float* bg = W   + ((size_t)(bn * 128 + lrow)) * DIM + lk;

    // compute mapping: 16x16 threads, 8x8 micro-tile each
    const int tx = tid & 15, ty = tid >> 4;
    const int rm = ty * 8, rn = tx * 8;

    float acc[8][8];
    #pragma unroll
    for (int i = 0; i < 8; i++)
        #pragma unroll
        for (int j = 0; j < 8; j++) acc[i][j] = 0.f;

    // prime buffer 0
    {
        float4 a = *reinterpret_cast<const float4*>(ag);
        float4 b = *reinterpret_cast<const float4*>(bg);
        As[0][lk + 0][lrow] = a.x; As[0][lk + 1][lrow] = a.y;
        As[0][lk + 2][lrow] = a.z; As[0][lk + 3][lrow] = a.w;
        Bs[0][lk + 0][lrow] = b.x; Bs[0][lk + 1][lrow] = b.y;
        Bs[0][lk + 2][lrow] = b.z; Bs[0][lk + 3][lrow] = b.w;
    }
    __syncthreads();

    int buf = 0;
    const int KT = DIM / 8;   // 64
    #pragma unroll 1
    for (int kt = 0; kt < KT; kt++) {
        float4 an, bn4;
        const bool more = (kt + 1 < KT);
        if (more) {
            an  = *reinterpret_cast<const float4*>(ag + (kt + 1) * 8);
            bn4 = *reinterpret_cast<const float4*>(bg + (kt + 1) * 8);
        }

        #pragma unroll
        for (int kk = 0; kk < 8; kk++) {
            float4 a0 = *reinterpret_cast<const float4*>(&As[buf][kk][rm]);
            float4 a1 = *reinterpret_cast<const float4*>(&As[buf][kk][rm + 4]);
            float4 b0 = *reinterpret_cast<const float4*>(&Bs[buf][kk][rn]);
            float4 b1 = *reinterpret_cast<const float4*>(&Bs[buf][kk][rn + 4]);
            float av[8] = {a0.x, a0.y, a0.z, a0.w, a1.x, a1.y, a1.z, a1.w};
            float bv[8] = {b0.x, b0.y, b0.z, b0.w, b1.x, b1.y, b1.z, b1.w};
            #pragma unroll
            for (int i = 0; i < 8; i++)
                #pragma unroll
                for (int j = 0; j < 8; j++)
                    acc[i][j] += av[i] * bv[j];
        }

        if (more) {
            const int nb = buf ^ 1;
            As[nb][lk + 0][lrow] = an.x;  As[nb][lk + 1][lrow] = an.y;
            As[nb][lk + 2][lrow] = an.z;  As[nb][lk + 3][lrow] = an.w;
            Bs[nb][lk + 0][lrow] = bn4.x; Bs[nb][lk + 1][lrow] = bn4.y;
            Bs[nb][lk + 2][lrow] = bn4.z; Bs[nb][lk + 3][lrow] = bn4.w;
            __syncthreads();
            buf = nb;
        }
    }

    // epilogue: vectorized stores
    float* op = out + (size_t)(bm * 128 + rm) * DIM + bn * 128 + rn;
    #pragma unroll
    for (int i = 0; i < 8; i++) {
        float4 v0 = make_float4(acc[i][0], acc[i][1], acc[i][2], acc[i][3]);
        float4 v1 = make_float4(acc[i][4], acc[i][5], acc[i][6], acc[i][7]);
        *reinterpret_cast<float4*>(op + (size_t)i * DIM)     = v0;
        *reinterpret_cast<float4*>(op + (size_t)i * DIM + 4) = v1;
    }
}

// ---------------------------------------------------------------------------
// kernel_launch: inputs (metadata order): x, weight, row, col, vals
// ---------------------------------------------------------------------------
extern "C" void kernel_launch(void* const* d_in, const int* in_sizes, int n_in,
                              void* d_out, int out_size) {
    const float* x      = (const float*)d_in[0];
    const float* weight = (const float*)d_in[1];
    const void*  row    = d_in[2];
    const void*  col    = d_in[3];
    const float* vals   = (const float*)d_in[4];
    float* out = (float*)d_out;

    (void)in_sizes; (void)n_in; (void)out_size;

    // 0) zero scratch + detector
    zero_kernel<<<512, 256>>>();

    // 1) index dtype detection (int32 vs int64)
    detect_kernel<<<128, 256>>>((const unsigned int*)row);

    // 2) Y = Adj @ X   (warp per edge, 8 edges/block)
    scatter_kernel<<<N_EDGES / 8, 256>>>(x, row, col, vals);

    // 3) out = Y @ W^T
    dim3 grid(DIM / 128, N_NODES / 128);   // (4, 512), N-tile fastest for Y L2 reuse
    gemm_kernel<<<grid, 256>>>(weight, out);
}

// round 9
// speedup vs baseline: 1.0018x; 1.0018x over previous
#include <cuda_runtime.h>
#include <cstdint>

#define N_NODES 65536
#define N_EDGES 524288
#define DIM     512

// Scratch: Y = Adj @ X  (fp32, 128 MB) — static device global (no allocs allowed)
__device__ float g_Y[(size_t)N_NODES * DIM];
// OR of odd 32-bit words of the row-index buffer: ==0  <=>  indices are int64
__device__ unsigned int g_or_hi;

// ---------------------------------------------------------------------------
// Kernel 0: zero Y scratch + reset dtype-detect accumulator
// ---------------------------------------------------------------------------
__global__ void __launch_bounds__(256) zero_kernel() {
    const size_t n4 = (size_t)N_NODES * DIM / 4;
    float4* p = reinterpret_cast<float4*>(g_Y);
    float4 z = make_float4(0.f, 0.f, 0.f, 0.f);
    for (size_t i = (size_t)blockIdx.x * blockDim.x + threadIdx.x; i < n4;
         i += (size_t)gridDim.x * blockDim.x)
        p[i] = z;
    if (blockIdx.x == 0 && threadIdx.x == 0) g_or_hi = 0u;
}

// ---------------------------------------------------------------------------
// Kernel 1: detect int32 vs int64 indices.
// Reads only the first N_EDGES 32-bit words (always in-bounds for both dtypes).
// int64 case: odd words are high halves of entries 0..N_EDGES/2-1 -> all 0.
// int32 case: odd words are random indices in [0,65536) -> OR != 0 w.p. ~1.
// ---------------------------------------------------------------------------
__global__ void __launch_bounds__(256) detect_kernel(const unsigned int* __restrict__ rowu) {
    unsigned int v = 0;
    for (int i = blockIdx.x * blockDim.x + threadIdx.x; i < N_EDGES / 2;
         i += gridDim.x * blockDim.x)
        v |= rowu[2 * i + 1];
    // warp reduce
    #pragma unroll
    for (int s = 16; s > 0; s >>= 1) v |= __shfl_xor_sync(0xFFFFFFFFu, v, s);
    if ((threadIdx.x & 31) == 0 && v) atomicOr(&g_or_hi, v);
}

// ---------------------------------------------------------------------------
// Kernel 2: scatter  Y[row[e]] += vals[e] * x[col[e]]
// One warp per edge; lane l handles float4 chunks l, l+32, l+64, l+96.
// Atomic addresses within a warp are consecutive -> coalesced 128B RMW groups.
// ---------------------------------------------------------------------------
__global__ void __launch_bounds__(256) scatter_kernel(const float* __restrict__ x,
                                                      const void*  __restrict__ rowp,
                                                      const void*  __restrict__ colp,
                                                      const float* __restrict__ vals) {
    const bool is64 = (g_or_hi == 0u);
    int e    = blockIdx.x * (blockDim.x >> 5) + (threadIdx.x >> 5);
    int lane = threadIdx.x & 31;
    if (e >= N_EDGES) return;

    int r, c;
    if (is64) {
        r = (int)reinterpret_cast<const long long*>(rowp)[e];
        c = (int)reinterpret_cast<const long long*>(colp)[e];
    } else {
        r = reinterpret_cast<const int*>(rowp)[e];
        c = reinterpret_cast<const int*>(colp)[e];
    }
    const float v = vals[e];

    const float4* xs = reinterpret_cast<const float4*>(x + (size_t)c * DIM);
    float* yd = g_Y + (size_t)r * DIM;

    #pragma unroll
    for (int i = 0; i < 4; i++) {
        int c4 = lane + 32 * i;          // float4 index within the row
        float4 t = xs[c4];
        int base = c4 * 4;
        atomicAdd(&yd[base + 0], v * t.x);
        atomicAdd(&yd[base + 1], v * t.y);
        atomicAdd(&yd[base + 2], v * t.z);
        atomicAdd(&yd[base + 3], v * t.w);
    }
}

// ---------------------------------------------------------------------------
// Kernel 3: out = Y @ W^T   (M=65536, N=512, K=512, all fp32, K-contiguous)
// Classic 128x128 block tile, K-step 8, double-buffered SMEM, 8x8 per thread.
// blockIdx.x = N-tile (4 values, fastest) so consecutive blocks reuse the same
// Y rows through L2 -> Y streamed from HBM ~once.
// ---------------------------------------------------------------------------
__global__ void __launch_bounds__(256) gemm_kernel(const float* __restrict__ W,
                                                   float* __restrict__ out) {
    __shared__ float As[2][8][128];
    __shared__ float Bs[2][8][128];

    const int bn = blockIdx.x;   // 0..3
    const int bm = blockIdx.y;   // 0..511
    const int tid = threadIdx.x;

    // loader mapping: 128 rows x 8 k = 1024 floats = 256 threads x float4
    const int lrow = tid >> 1;
    const int lk   = (tid & 1) * 4;
    const float* ag = g_Y + ((size_t)(bm * 128 + lrow)) * DIM + lk;
    const float* bg = W   + ((size_t)(bn * 128 + lrow)) * DIM + lk;

    // compute mapping: 16x16 threads, 8x8 micro-tile each
    const int tx = tid & 15, ty = tid >> 4;
    const int rm = ty * 8, rn = tx * 8;

    float acc[8][8];
    #pragma unroll
    for (int i = 0; i < 8; i++)
        #pragma unroll
        for (int j = 0; j < 8; j++) acc[i][j] = 0.f;

    // prime buffer 0
    {
        float4 a = *reinterpret_cast<const float4*>(ag);
        float4 b = *reinterpret_cast<const float4*>(bg);
        As[0][lk + 0][lrow] = a.x; As[0][lk + 1][lrow] = a.y;
        As[0][lk + 2][lrow] = a.z; As[0][lk + 3][lrow] = a.w;
        Bs[0][lk + 0][lrow] = b.x; Bs[0][lk + 1][lrow] = b.y;
        Bs[0][lk + 2][lrow] = b.z; Bs[0][lk + 3][lrow] = b.w;
    }
    __syncthreads();

    int buf = 0;
    const int KT = DIM / 8;   // 64
    #pragma unroll 1
    for (int kt = 0; kt < KT; kt++) {
        float4 an, bn4;
        const bool more = (kt + 1 < KT);
        if (more) {
            an  = *reinterpret_cast<const float4*>(ag + (kt + 1) * 8);
            bn4 = *reinterpret_cast<const float4*>(bg + (kt + 1) * 8);
        }

        #pragma unroll
        for (int kk = 0; kk < 8; kk++) {
            float4 a0 = *reinterpret_cast<const float4*>(&As[buf][kk][rm]);
            float4 a1 = *reinterpret_cast<const float4*>(&As[buf][kk][rm + 4]);
            float4 b0 = *reinterpret_cast<const float4*>(&Bs[buf][kk][rn]);
            float4 b1 = *reinterpret_cast<const float4*>(&Bs[buf][kk][rn + 4]);
            float av[8] = {a0.x, a0.y, a0.z, a0.w, a1.x, a1.y, a1.z, a1.w};
            float bv[8] = {b0.x, b0.y, b0.z, b0.w, b1.x, b1.y, b1.z, b1.w};
            #pragma unroll
            for (int i = 0; i < 8; i++)
                #pragma unroll
                for (int j = 0; j < 8; j++)
                    acc[i][j] += av[i] * bv[j];
        }

        if (more) {
            const int nb = buf ^ 1;
            As[nb][lk + 0][lrow] = an.x;  As[nb][lk + 1][lrow] = an.y;
            As[nb][lk + 2][lrow] = an.z;  As[nb][lk + 3][lrow] = an.w;
            Bs[nb][lk + 0][lrow] = bn4.x; Bs[nb][lk + 1][lrow] = bn4.y;
            Bs[nb][lk + 2][lrow] = bn4.z; Bs[nb][lk + 3][lrow] = bn4.w;
            __syncthreads();
            buf = nb;
        }
    }

    // epilogue: vectorized stores
    float* op = out + (size_t)(bm * 128 + rm) * DIM + bn * 128 + rn;
    #pragma unroll
    for (int i = 0; i < 8; i++) {
        float4 v0 = make_float4(acc[i][0], acc[i][1], acc[i][2], acc[i][3]);
        float4 v1 = make_float4(acc[i][4], acc[i][5], acc[i][6], acc[i][7]);
        *reinterpret_cast<float4*>(op + (size_t)i * DIM)     = v0;
        *reinterpret_cast<float4*>(op + (size_t)i * DIM + 4) = v1;
    }
}

// ---------------------------------------------------------------------------
// kernel_launch: inputs (metadata order): x, weight, row, col, vals
// ---------------------------------------------------------------------------
extern "C" void kernel_launch(void* const* d_in, const int* in_sizes, int n_in,
                              void* d_out, int out_size) {
    const float* x      = (const float*)d_in[0];
    const float* weight = (const float*)d_in[1];
    const void*  row    = d_in[2];
    const void*  col    = d_in[3];
    const float* vals   = (const float*)d_in[4];
    float* out = (float*)d_out;

    (void)in_sizes; (void)n_in; (void)out_size;

    // 0) zero scratch + detector
    zero_kernel<<<512, 256>>>();

    // 1) index dtype detection (int32 vs int64)
    detect_kernel<<<128, 256>>>((const unsigned int*)row);

    // 2) Y = Adj @ X   (warp per edge, 8 edges/block)
    scatter_kernel<<<N_EDGES / 8, 256>>>(x, row, col, vals);

    // 3) out = Y @ W^T
    dim3 grid(DIM / 128, N_NODES / 128);   // (4, 512), N-tile fastest for Y L2 reuse
    gemm_kernel<<<grid, 256>>>(weight, out);
}